// round 5
// baseline (speedup 1.0000x reference)
#include <cuda_runtime.h>
#include <cuda_bf16.h>
#include <cstdint>

#define N_NODES 100000
#define F_IN    500
#define HID     256
#define C_OUT   40
#define ALPHA0  0.1f
#define K_PAD   512
#define BK      32
#define NCHUNK  16
#define BM      128
#define N2      64
#define E_MAX   2400000

// ---------------------------------------------------------------------------
// Device-global scratch (allocation-free rule)
// ---------------------------------------------------------------------------
__device__ float g_h2[(size_t)N_NODES * C_OUT];                       // 16 MB
__device__ __align__(16) __nv_bfloat16 g_w1t_hi[HID * K_PAD];
__device__ __align__(16) __nv_bfloat16 g_w1t_lo[HID * K_PAD];
__device__ __align__(16) __nv_bfloat16 g_w2t_hi[N2 * HID];
__device__ __align__(16) __nv_bfloat16 g_w2t_lo[N2 * HID];
// sort scratch
__device__ int   g_cnt[N_NODES + 1];
__device__ int   g_excl[N_NODES + 1];
__device__ int   g_bsum[128];
__device__ int   g_boff[128];
__device__ int   g_start[N_NODES + 1];
__device__ int   g_cur[N_NODES];
__device__ int   g_scol[E_MAX];
__device__ float g_sval[E_MAX];

// ---------------------------------------------------------------------------
// Helpers
// ---------------------------------------------------------------------------
__device__ __forceinline__ uint32_t smem_u32(const void* p) {
    uint32_t a;
    asm("{ .reg .u64 t; cvta.to.shared.u64 t, %1; cvt.u32.u64 %0, t; }" : "=r"(a) : "l"(p));
    return a;
}

__device__ __forceinline__ uint32_t pack_bf2(float lo, float hi) {
    uint32_t r;
    asm("cvt.rn.bf16x2.f32 %0, %1, %2;" : "=r"(r) : "f"(hi), "f"(lo));
    return r;
}
__device__ __forceinline__ float bf_lo(uint32_t w) { return __uint_as_float(w << 16); }
__device__ __forceinline__ float bf_hi(uint32_t w) { return __uint_as_float(w & 0xffff0000u); }

__device__ __forceinline__ void mma_bf16(float d[4], const uint32_t a[4], const uint32_t b[2]) {
    asm volatile("mma.sync.aligned.m16n8k16.row.col.f32.bf16.bf16.f32 "
                 "{%0,%1,%2,%3},{%4,%5,%6,%7},{%8,%9},{%0,%1,%2,%3};"
                 : "+f"(d[0]), "+f"(d[1]), "+f"(d[2]), "+f"(d[3])
                 : "r"(a[0]), "r"(a[1]), "r"(a[2]), "r"(a[3]), "r"(b[0]), "r"(b[1]));
}

#define CP_ASYNC16(dst, src) \
    asm volatile("cp.async.cg.shared.global [%0], [%1], 16;" :: "r"(dst), "l"(src))
#define CP_COMMIT() asm volatile("cp.async.commit_group;" ::: "memory")
#define CP_WAIT0()  asm volatile("cp.async.wait_group 0;" ::: "memory")

// ---------------------------------------------------------------------------
// Dynamic SMEM layout (bytes) — unchanged from R4
// ---------------------------------------------------------------------------
#define APAD 40
#define SA_HI(b) ((b) * 61440)
#define SA_LO(b) ((b) * 61440 + 10240)
#define SB_HI(b) ((b) * 61440 + 20480)
#define SB_LO(b) ((b) * 61440 + 40960)
#define HPAD 264
#define SH_HI 0
#define SH_LO 67584
#define SW_HI 135168
#define SW_LO 168960
#define DSMEM_BYTES 202752

// ---------------------------------------------------------------------------
// Prep: bf16 hi/lo images of W1^T (bias folded at k=500) and W2^T (pad 40->64)
// ---------------------------------------------------------------------------
__global__ void prep_kernel(const float* __restrict__ W1,
                            const float* __restrict__ b1,
                            const float* __restrict__ W2)
{
    const int idx = blockIdx.x * blockDim.x + threadIdx.x;
    if (idx < HID * K_PAD) {
        const int n = idx >> 9;
        const int k = idx & (K_PAD - 1);
        float v = 0.f;
        if (k < F_IN)       v = W1[(size_t)k * HID + n];
        else if (k == F_IN) v = b1[n];
        const __nv_bfloat16 h = __float2bfloat16_rn(v);
        g_w1t_hi[idx] = h;
        g_w1t_lo[idx] = __float2bfloat16_rn(v - __bfloat162float(h));
    } else {
        const int i = idx - HID * K_PAD;
        if (i < N2 * HID) {
            const int n = i >> 8;
            const int k = i & 255;
            const float v = (n < C_OUT) ? W2[(size_t)k * C_OUT + n] : 0.f;
            const __nv_bfloat16 h = __float2bfloat16_rn(v);
            g_w2t_hi[i] = h;
            g_w2t_lo[i] = __float2bfloat16_rn(v - __bfloat162float(h));
        }
    }
}

// ---------------------------------------------------------------------------
// Fused GEMM1(+bias+ReLU)+GEMM2(+bias) via mma.sync bf16 split (3 terms).
// (unchanged from R4 — writes g_h2 and out = ALPHA0*h2)
// ---------------------------------------------------------------------------
#define LOADA(c) do {                                                          \
    const int gk = (c) * BK + akq;                                             \
    _Pragma("unroll")                                                          \
    for (int rr = 0; rr < 4; rr++) {                                           \
        const int grow = blockRow + ar + rr * 32;                              \
        float4 v = make_float4(0.f, 0.f, 0.f, 0.f);                            \
        if (grow < N_NODES) {                                                  \
            if (gk + 3 < F_IN) {                                               \
                v = *(const float4*)(x + (size_t)grow * F_IN + gk);            \
            } else {                                                           \
                const float* xr = x + (size_t)grow * F_IN;                     \
                v.x = (gk + 0 < F_IN) ? xr[gk + 0] : (gk + 0 == F_IN ? 1.f : 0.f); \
                v.y = (gk + 1 < F_IN) ? xr[gk + 1] : (gk + 1 == F_IN ? 1.f : 0.f); \
                v.z = (gk + 2 < F_IN) ? xr[gk + 2] : (gk + 2 == F_IN ? 1.f : 0.f); \
                v.w = (gk + 3 < F_IN) ? xr[gk + 3] : (gk + 3 == F_IN ? 1.f : 0.f); \
            }                                                                  \
        }                                                                      \
        av[rr] = v;                                                            \
    }                                                                          \
} while (0)

#define STSA(buf) do {                                                         \
    _Pragma("unroll")                                                          \
    for (int rr = 0; rr < 4; rr++) {                                           \
        const int o = (ar + rr * 32) * APAD + akq;                             \
        const uint32_t h0 = pack_bf2(av[rr].x, av[rr].y);                      \
        const uint32_t h1 = pack_bf2(av[rr].z, av[rr].w);                      \
        const uint32_t l0 = pack_bf2(av[rr].x - bf_lo(h0), av[rr].y - bf_hi(h0)); \
        const uint32_t l1 = pack_bf2(av[rr].z - bf_lo(h1), av[rr].w - bf_hi(h1)); \
        *(uint2*)(dsm + SA_HI(buf) + o * 2) = make_uint2(h0, h1);              \
        *(uint2*)(dsm + SA_LO(buf) + o * 2) = make_uint2(l0, l1);              \
    }                                                                          \
} while (0)

#define CPB(c, buf) do {                                                       \
    const uint32_t dhi = smbase + SB_HI(buf) + tid * (APAD * 2);               \
    const uint32_t dlo = smbase + SB_LO(buf) + tid * (APAD * 2);               \
    const __nv_bfloat16* shi = g_w1t_hi + (size_t)tid * K_PAD + (c) * BK;      \
    const __nv_bfloat16* slo = g_w1t_lo + (size_t)tid * K_PAD + (c) * BK;      \
    _Pragma("unroll")                                                          \
    for (int q = 0; q < 4; q++) {                                              \
        CP_ASYNC16(dhi + q * 16, shi + q * 8);                                 \
        CP_ASYNC16(dlo + q * 16, slo + q * 8);                                 \
    }                                                                          \
} while (0)

#define MMACHUNK(buf) do {                                                     \
    _Pragma("unroll")                                                          \
    for (int s = 0; s < 2; s++) {                                              \
        const int kk = s * 16 + tid4 * 2;                                      \
        uint32_t Bh[8][2], Bl[8][2];                                           \
        _Pragma("unroll")                                                      \
        for (int j = 0; j < 8; j++) {                                          \
            const int o = (wn * 64 + j * 8 + grp) * APAD + kk;                 \
            Bh[j][0] = *(const uint32_t*)(dsm + SB_HI(buf) + o * 2);           \
            Bh[j][1] = *(const uint32_t*)(dsm + SB_HI(buf) + (o + 8) * 2);     \
            Bl[j][0] = *(const uint32_t*)(dsm + SB_LO(buf) + o * 2);           \
            Bl[j][1] = *(const uint32_t*)(dsm + SB_LO(buf) + (o + 8) * 2);     \
        }                                                                      \
        _Pragma("unroll")                                                      \
        for (int i = 0; i < 4; i++) {                                          \
            const int o1 = (wm * 64 + i * 16 + grp) * APAD + kk;               \
            const int o2 = o1 + 8 * APAD;                                      \
            uint32_t Ah[4], Al[4];                                             \
            Ah[0] = *(const uint32_t*)(dsm + SA_HI(buf) + o1 * 2);             \
            Ah[1] = *(const uint32_t*)(dsm + SA_HI(buf) + o2 * 2);             \
            Ah[2] = *(const uint32_t*)(dsm + SA_HI(buf) + (o1 + 8) * 2);       \
            Ah[3] = *(const uint32_t*)(dsm + SA_HI(buf) + (o2 + 8) * 2);       \
            Al[0] = *(const uint32_t*)(dsm + SA_LO(buf) + o1 * 2);             \
            Al[1] = *(const uint32_t*)(dsm + SA_LO(buf) + o2 * 2);             \
            Al[2] = *(const uint32_t*)(dsm + SA_LO(buf) + (o1 + 8) * 2);       \
            Al[3] = *(const uint32_t*)(dsm + SA_LO(buf) + (o2 + 8) * 2);       \
            _Pragma("unroll")                                                  \
            for (int j = 0; j < 8; j++) {                                      \
                mma_bf16(acc[i][j], Ah, Bh[j]);                                \
                mma_bf16(acc[i][j], Ah, Bl[j]);                                \
                mma_bf16(acc[i][j], Al, Bh[j]);                                \
            }                                                                  \
        }                                                                      \
    }                                                                          \
} while (0)

__global__ void __launch_bounds__(256, 1) fused_kernel(
    const float* __restrict__ x,
    const float* __restrict__ b2,
    float* __restrict__ out)
{
    extern __shared__ char dsm[];
    __shared__ float s_b2[C_OUT];
    const uint32_t smbase = smem_u32(dsm);
    const int tid  = threadIdx.x;
    const int lane = tid & 31, wid = tid >> 5;
    const int grp  = lane >> 2, tid4 = lane & 3;
    const int wm   = wid >> 2, wn = wid & 3;
    const int blockRow = blockIdx.x * BM;

    if (tid < C_OUT) s_b2[tid] = b2[tid];

    const int ar  = tid >> 3;
    const int akq = (tid & 7) * 4;

    float acc[4][8][4];
    #pragma unroll
    for (int i = 0; i < 4; i++)
        #pragma unroll
        for (int j = 0; j < 8; j++)
            #pragma unroll
            for (int q = 0; q < 4; q++)
                acc[i][j][q] = 0.f;

    float4 av[4];

    LOADA(0);
    CPB(0, 0);
    CP_COMMIT();
    STSA(0);
    CP_WAIT0();
    __syncthreads();

    for (int c = 0; c < NCHUNK; c++) {
        const int cur = c & 1, nxt = cur ^ 1;
        if (c + 1 < NCHUNK) {
            LOADA(c + 1);
            CPB(c + 1, nxt);
            CP_COMMIT();
        }
        MMACHUNK(cur);
        if (c + 1 < NCHUNK) {
            STSA(nxt);
            CP_WAIT0();
        }
        __syncthreads();
    }

    #pragma unroll
    for (int i = 0; i < 4; i++) {
        const int r1 = wm * 64 + i * 16 + grp;
        #pragma unroll
        for (int j = 0; j < 8; j++) {
            const int col = wn * 64 + j * 8 + tid4 * 2;
            const float f0 = fmaxf(acc[i][j][0], 0.f), f1 = fmaxf(acc[i][j][1], 0.f);
            const float f2 = fmaxf(acc[i][j][2], 0.f), f3 = fmaxf(acc[i][j][3], 0.f);
            const uint32_t h0 = pack_bf2(f0, f1);
            const uint32_t l0 = pack_bf2(f0 - bf_lo(h0), f1 - bf_hi(h0));
            const uint32_t h1w = pack_bf2(f2, f3);
            const uint32_t l1w = pack_bf2(f2 - bf_lo(h1w), f3 - bf_hi(h1w));
            const int o1 = r1 * HPAD + col;
            const int o2 = o1 + 8 * HPAD;
            *(uint32_t*)(dsm + SH_HI + o1 * 2) = h0;
            *(uint32_t*)(dsm + SH_LO + o1 * 2) = l0;
            *(uint32_t*)(dsm + SH_HI + o2 * 2) = h1w;
            *(uint32_t*)(dsm + SH_LO + o2 * 2) = l1w;
        }
    }
    {
        const int n  = tid >> 2;
        const int kq = (tid & 3) * 64;
        #pragma unroll
        for (int q = 0; q < 8; q++) {
            const uint4 vh = *(const uint4*)(g_w2t_hi + n * HID + kq + q * 8);
            const uint4 vl = *(const uint4*)(g_w2t_lo + n * HID + kq + q * 8);
            *(uint4*)(dsm + SW_HI + (n * HPAD + kq + q * 8) * 2) = vh;
            *(uint4*)(dsm + SW_LO + (n * HPAD + kq + q * 8) * 2) = vl;
        }
    }
    __syncthreads();

    float acc2[8][4];
    #pragma unroll
    for (int j = 0; j < 8; j++)
        #pragma unroll
        for (int q = 0; q < 4; q++)
            acc2[j][q] = 0.f;

    #pragma unroll
    for (int s = 0; s < 16; s++) {
        const int kk = s * 16 + tid4 * 2;
        const int o1 = (wid * 16 + grp) * HPAD + kk;
        const int o2 = o1 + 8 * HPAD;
        uint32_t Ah[4], Al[4];
        Ah[0] = *(const uint32_t*)(dsm + SH_HI + o1 * 2);
        Ah[1] = *(const uint32_t*)(dsm + SH_HI + o2 * 2);
        Ah[2] = *(const uint32_t*)(dsm + SH_HI + (o1 + 8) * 2);
        Ah[3] = *(const uint32_t*)(dsm + SH_HI + (o2 + 8) * 2);
        Al[0] = *(const uint32_t*)(dsm + SH_LO + o1 * 2);
        Al[1] = *(const uint32_t*)(dsm + SH_LO + o2 * 2);
        Al[2] = *(const uint32_t*)(dsm + SH_LO + (o1 + 8) * 2);
        Al[3] = *(const uint32_t*)(dsm + SH_LO + (o2 + 8) * 2);
        #pragma unroll
        for (int j = 0; j < 8; j++) {
            const int ob = (j * 8 + grp) * HPAD + kk;
            uint32_t Bh[2], Bl[2];
            Bh[0] = *(const uint32_t*)(dsm + SW_HI + ob * 2);
            Bh[1] = *(const uint32_t*)(dsm + SW_HI + (ob + 8) * 2);
            Bl[0] = *(const uint32_t*)(dsm + SW_LO + ob * 2);
            Bl[1] = *(const uint32_t*)(dsm + SW_LO + (ob + 8) * 2);
            mma_bf16(acc2[j], Ah, Bh);
            mma_bf16(acc2[j], Ah, Bl);
            mma_bf16(acc2[j], Al, Bh);
        }
    }

    {
        const int r1 = blockRow + wid * 16 + grp;
        const int r2 = r1 + 8;
        #pragma unroll
        for (int j = 0; j < 5; j++) {
            const int col = j * 8 + tid4 * 2;
            const float b0 = s_b2[col], b1v = s_b2[col + 1];
            if (r1 < N_NODES) {
                const float v0 = acc2[j][0] + b0, v1 = acc2[j][1] + b1v;
                *(float2*)(g_h2 + (size_t)r1 * C_OUT + col) = make_float2(v0, v1);
                *(float2*)(out  + (size_t)r1 * C_OUT + col) = make_float2(ALPHA0 * v0, ALPHA0 * v1);
            }
            if (r2 < N_NODES) {
                const float v2 = acc2[j][2] + b0, v3 = acc2[j][3] + b1v;
                *(float2*)(g_h2 + (size_t)r2 * C_OUT + col) = make_float2(v2, v3);
                *(float2*)(out  + (size_t)r2 * C_OUT + col) = make_float2(ALPHA0 * v2, ALPHA0 * v3);
            }
        }
    }
}

// ---------------------------------------------------------------------------
// Counting sort of edges by destination row, then gather-SpMM (no atomic REDs)
// ---------------------------------------------------------------------------
__global__ void __launch_bounds__(256) hist_kernel(const int* __restrict__ erow,
                                                   long long num_edges)
{
    const long long e = (long long)blockIdx.x * blockDim.x + threadIdx.x;
    if (e < num_edges) atomicAdd(&g_cnt[erow[e]], 1);
}

__global__ void __launch_bounds__(1024) scan1_kernel()
{
    __shared__ int sh[1024];
    const int t = threadIdx.x;
    const int i = blockIdx.x * 1024 + t;
    const int v = (i <= N_NODES) ? g_cnt[i] : 0;
    sh[t] = v;
    __syncthreads();
    #pragma unroll
    for (int off = 1; off < 1024; off <<= 1) {
        int add = (t >= off) ? sh[t - off] : 0;
        __syncthreads();
        sh[t] += add;
        __syncthreads();
    }
    if (i <= N_NODES) g_excl[i] = sh[t] - v;
    if (t == 1023) g_bsum[blockIdx.x] = sh[t];
}

__global__ void scan2_kernel(int nblocks)
{
    if (threadIdx.x == 0) {
        int run = 0;
        for (int b = 0; b < nblocks; b++) {
            g_boff[b] = run;
            run += g_bsum[b];
        }
    }
}

__global__ void __launch_bounds__(256) scan3_kernel()
{
    const int i = blockIdx.x * blockDim.x + threadIdx.x;
    if (i <= N_NODES) {
        const int s = g_excl[i] + g_boff[i >> 10];
        g_start[i] = s;
        if (i < N_NODES) g_cur[i] = s;
    }
}

__global__ void __launch_bounds__(256) scatter_kernel(
    const int* __restrict__ erow,
    const int* __restrict__ ecol,
    const float* __restrict__ eval,
    long long num_edges)
{
    const long long e = (long long)blockIdx.x * blockDim.x + threadIdx.x;
    if (e >= num_edges) return;
    const int r = erow[e];
    const int pos = atomicAdd(&g_cur[r], 1);
    g_scol[pos] = ecol[e];
    g_sval[pos] = eval[e];
}

// 10 threads per node; each owns one float4 slice of the 40-float row.
__global__ void __launch_bounds__(256) gather_kernel(float* __restrict__ out)
{
    const long long gid = (long long)blockIdx.x * blockDim.x + threadIdx.x;
    const int node = (int)(gid / 10);
    if (node >= N_NODES) return;
    const int sub = (int)(gid % 10);

    const int s = g_start[node];
    const int epos = g_start[node + 1];

    float4 acc = make_float4(0.f, 0.f, 0.f, 0.f);
    for (int i = s; i < epos; i++) {
        const int c = __ldg(&g_scol[i]);
        const float v = __ldg(&g_sval[i]);
        const float4 h = reinterpret_cast<const float4*>(g_h2 + (size_t)c * C_OUT)[sub];
        acc.x += v * h.x;
        acc.y += v * h.y;
        acc.z += v * h.z;
        acc.w += v * h.w;
    }

    float4* o = reinterpret_cast<float4*>(out + (size_t)node * C_OUT) + sub;
    float4 cur = *o;          // out already holds ALPHA0 * h2
    cur.x += acc.x; cur.y += acc.y; cur.z += acc.z; cur.w += acc.w;
    *o = cur;
}

// ---------------------------------------------------------------------------
// log_softmax over C=40, one warp per row, in place.
// ---------------------------------------------------------------------------
__global__ void __launch_bounds__(256) logsoftmax_kernel(float* __restrict__ out)
{
    const int warp = (blockIdx.x * blockDim.x + threadIdx.x) >> 5;
    const int lane = threadIdx.x & 31;
    if (warp >= N_NODES) return;

    float* row = out + (size_t)warp * C_OUT;
    const float v0 = (lane < C_OUT) ? row[lane] : -__int_as_float(0x7f800000);
    const float v1 = (lane + 32 < C_OUT) ? row[lane + 32] : -__int_as_float(0x7f800000);

    float m = fmaxf(v0, v1);
    #pragma unroll
    for (int o = 16; o > 0; o >>= 1)
        m = fmaxf(m, __shfl_xor_sync(0xffffffffu, m, o));

    float s = ((lane < C_OUT) ? expf(v0 - m) : 0.f)
            + ((lane + 32 < C_OUT) ? expf(v1 - m) : 0.f);
    #pragma unroll
    for (int o = 16; o > 0; o >>= 1)
        s += __shfl_xor_sync(0xffffffffu, s, o);

    const float lse = m + logf(s);
    if (lane < C_OUT) row[lane] = v0 - lse;
    if (lane + 32 < C_OUT) row[lane + 32] = v1 - lse;
}

// ---------------------------------------------------------------------------
// Inputs: x, W1, b1, W2, b2, edge_row, edge_col, edge_val
// ---------------------------------------------------------------------------
extern "C" void kernel_launch(void* const* d_in, const int* in_sizes, int n_in,
                              void* d_out, int out_size)
{
    const float* x    = (const float*)d_in[0];
    const float* W1   = (const float*)d_in[1];
    const float* b1   = (const float*)d_in[2];
    const float* W2   = (const float*)d_in[3];
    const float* b2   = (const float*)d_in[4];
    const int*   erow = (const int*)d_in[5];
    const int*   ecol = (const int*)d_in[6];
    const float* eval = (const float*)d_in[7];
    float* out = (float*)d_out;

    const long long E = in_sizes[5];

    cudaFuncSetAttribute(fused_kernel,
                         cudaFuncAttributeMaxDynamicSharedMemorySize, DSMEM_BYTES);

    // prep weight images
    {
        const int total = HID * K_PAD + N2 * HID;
        prep_kernel<<<(total + 255) / 256, 256>>>(W1, b1, W2);
    }

    // ---- counting sort of edges by destination row ----
    {
        void* cnt_ptr = nullptr;
        cudaGetSymbolAddress(&cnt_ptr, g_cnt);
        cudaMemsetAsync(cnt_ptr, 0, sizeof(int) * (N_NODES + 1));

        hist_kernel<<<(int)((E + 255) / 256), 256>>>(erow, E);

        const int nblocks = (N_NODES + 1 + 1023) / 1024;   // 98
        scan1_kernel<<<nblocks, 1024>>>();
        scan2_kernel<<<1, 32>>>(nblocks);
        scan3_kernel<<<(N_NODES + 1 + 255) / 256, 256>>>();

        scatter_kernel<<<(int)((E + 255) / 256), 256>>>(erow, ecol, eval, E);
    }

    // fused GEMM1+GEMM2 (mma.sync bf16 split) -> g_h2, out = alpha*h2
    {
        const int blocks = (N_NODES + BM - 1) / BM;
        fused_kernel<<<blocks, 256, DSMEM_BYTES>>>(x, b2, out);
    }

    // gather-SpMM: out[r] += sum_e val * h2[col]
    {
        const long long total = (long long)N_NODES * 10;
        gather_kernel<<<(int)((total + 255) / 256), 256>>>(out);
    }

    // log_softmax
    {
        const long long threads = (long long)N_NODES * 32;
        logsoftmax_kernel<<<(int)((threads + 255) / 256), 256>>>(out);
    }
}

// round 6
// speedup vs baseline: 1.1130x; 1.1130x over previous
#include <cuda_runtime.h>
#include <cuda_bf16.h>
#include <cstdint>

#define N_NODES 100000
#define F_IN    500
#define HID     256
#define C_OUT   40
#define ALPHA0  0.1f
#define K_PAD   512
#define BK      32
#define NCHUNK  16
#define BM      128
#define N2      48

// ---------------------------------------------------------------------------
// Device-global scratch (allocation-free rule)
// ---------------------------------------------------------------------------
__device__ float g_h2[(size_t)N_NODES * C_OUT];                       // 16 MB
__device__ __align__(16) __nv_bfloat16 g_w1t_hi[HID * K_PAD];
__device__ __align__(16) __nv_bfloat16 g_w1t_lo[HID * K_PAD];
__device__ __align__(16) __nv_bfloat16 g_w2t_hi[N2 * HID];
__device__ __align__(16) __nv_bfloat16 g_w2t_lo[N2 * HID];

// ---------------------------------------------------------------------------
// Helpers
// ---------------------------------------------------------------------------
__device__ __forceinline__ uint32_t smem_u32(const void* p) {
    uint32_t a;
    asm("{ .reg .u64 t; cvta.to.shared.u64 t, %1; cvt.u32.u64 %0, t; }" : "=r"(a) : "l"(p));
    return a;
}

__device__ __forceinline__ uint32_t pack_bf2(float lo, float hi) {
    uint32_t r;
    asm("cvt.rn.bf16x2.f32 %0, %1, %2;" : "=r"(r) : "f"(hi), "f"(lo));
    return r;
}
__device__ __forceinline__ float bf_lo(uint32_t w) { return __uint_as_float(w << 16); }
__device__ __forceinline__ float bf_hi(uint32_t w) { return __uint_as_float(w & 0xffff0000u); }

__device__ __forceinline__ void mma_bf16(float d[4], const uint32_t a[4], const uint32_t b[2]) {
    asm volatile("mma.sync.aligned.m16n8k16.row.col.f32.bf16.bf16.f32 "
                 "{%0,%1,%2,%3},{%4,%5,%6,%7},{%8,%9},{%0,%1,%2,%3};"
                 : "+f"(d[0]), "+f"(d[1]), "+f"(d[2]), "+f"(d[3])
                 : "r"(a[0]), "r"(a[1]), "r"(a[2]), "r"(a[3]), "r"(b[0]), "r"(b[1]));
}

#define CP_ASYNC16(dst, src) \
    asm volatile("cp.async.cg.shared.global [%0], [%1], 16;" :: "r"(dst), "l"(src))
#define CP_COMMIT() asm volatile("cp.async.commit_group;" ::: "memory")
#define CP_WAIT0()  asm volatile("cp.async.wait_group 0;" ::: "memory")

// ---------------------------------------------------------------------------
// Dynamic SMEM layout (bytes)
// Stage 1, two buffers of 61440B:
//   sA_hi[128][40]b16 | sA_lo | sB_hi[256][40] | sB_lo
// Stage 2 (reuses region):
//   sH_hi[128][264] | sH_lo | sW_hi[48][264] | sW_lo
// ---------------------------------------------------------------------------
#define APAD 40
#define SA_HI(b) ((b) * 61440)
#define SA_LO(b) ((b) * 61440 + 10240)
#define SB_HI(b) ((b) * 61440 + 20480)
#define SB_LO(b) ((b) * 61440 + 40960)
#define HPAD 264
#define SH_HI 0
#define SH_LO 67584
#define SW_HI 135168
#define SW_LO 160512
#define DSMEM_BYTES 185856

// ---------------------------------------------------------------------------
// Prep: bf16 hi/lo images of W1^T (bias folded at k=500) and W2^T (pad 40->48)
// ---------------------------------------------------------------------------
__global__ void prep_kernel(const float* __restrict__ W1,
                            const float* __restrict__ b1,
                            const float* __restrict__ W2)
{
    const int idx = blockIdx.x * blockDim.x + threadIdx.x;
    if (idx < HID * K_PAD) {
        const int n = idx >> 9;
        const int k = idx & (K_PAD - 1);
        float v = 0.f;
        if (k < F_IN)       v = W1[(size_t)k * HID + n];
        else if (k == F_IN) v = b1[n];
        const __nv_bfloat16 h = __float2bfloat16_rn(v);
        g_w1t_hi[idx] = h;
        g_w1t_lo[idx] = __float2bfloat16_rn(v - __bfloat162float(h));
    } else {
        const int i = idx - HID * K_PAD;
        if (i < N2 * HID) {
            const int n = i >> 8;
            const int k = i & 255;
            const float v = (n < C_OUT) ? W2[(size_t)k * C_OUT + n] : 0.f;
            const __nv_bfloat16 h = __float2bfloat16_rn(v);
            g_w2t_hi[i] = h;
            g_w2t_lo[i] = __float2bfloat16_rn(v - __bfloat162float(h));
        }
    }
}

// ---------------------------------------------------------------------------
// Fused GEMM1(+bias+ReLU)+GEMM2(+bias), mma.sync bf16 split (3 terms).
// 512 threads / 16 warps, warp tile 32x64 in GEMM1.
// ---------------------------------------------------------------------------
__global__ void __launch_bounds__(512, 1) fused_kernel(
    const float* __restrict__ x,
    const float* __restrict__ b2,
    float* __restrict__ out)
{
    extern __shared__ char dsm[];
    __shared__ float s_b2[C_OUT];
    const uint32_t smbase = smem_u32(dsm);
    const int tid  = threadIdx.x;
    const int lane = tid & 31, wid = tid >> 5;
    const int grp  = lane >> 2, tid4 = lane & 3;
    const int wm   = wid >> 2, wn = wid & 3;      // wm,wn in 0..3
    const int blockRow = blockIdx.x * BM;

    if (tid < C_OUT) s_b2[tid] = b2[tid];

    // A global-load mapping: 128 rows x 4 threads, 8 floats each
    const int ar   = tid >> 2;
    const int akq8 = (tid & 2) * 8 + (tid & 1) * 4;   // 0,4,16,20 pattern? -> use simple:
    // (use (tid&3)*8 so each thread covers 8 contiguous k; two float4 loads)
    const int akq  = (tid & 3) * 8;
    (void)akq8;

    // B cp.async mapping: 256 rows x 2 threads, 16B (8 bf16) each
    const int brow = tid >> 1;
    const int bseg = tid & 1;

    float acc[2][8][4];
    #pragma unroll
    for (int i = 0; i < 2; i++)
        #pragma unroll
        for (int j = 0; j < 8; j++)
            #pragma unroll
            for (int q = 0; q < 4; q++)
                acc[i][j][q] = 0.f;

    const int grow = blockRow + ar;
    const bool rok = grow < N_NODES;
    const float* xrow = x + (size_t)grow * F_IN;

    float4 av[2];

    // ---- helpers as lambdas ----
    auto loadA = [&](int c) {
        const int gk0 = c * BK + akq;
        #pragma unroll
        for (int h = 0; h < 2; h++) {
            const int gk = gk0 + h * 4;
            float4 v = make_float4(0.f, 0.f, 0.f, 0.f);
            if (rok) {
                if (gk + 3 < F_IN) {
                    v = *(const float4*)(xrow + gk);
                } else {
                    v.x = (gk + 0 < F_IN) ? xrow[gk + 0] : (gk + 0 == F_IN ? 1.f : 0.f);
                    v.y = (gk + 1 < F_IN) ? xrow[gk + 1] : (gk + 1 == F_IN ? 1.f : 0.f);
                    v.z = (gk + 2 < F_IN) ? xrow[gk + 2] : (gk + 2 == F_IN ? 1.f : 0.f);
                    v.w = (gk + 3 < F_IN) ? xrow[gk + 3] : (gk + 3 == F_IN ? 1.f : 0.f);
                }
            }
            av[h] = v;
        }
    };
    auto stsA = [&](int buf) {
        #pragma unroll
        for (int h = 0; h < 2; h++) {
            const int o = ar * APAD + akq + h * 4;
            const uint32_t h0 = pack_bf2(av[h].x, av[h].y);
            const uint32_t h1 = pack_bf2(av[h].z, av[h].w);
            const uint32_t l0 = pack_bf2(av[h].x - bf_lo(h0), av[h].y - bf_hi(h0));
            const uint32_t l1 = pack_bf2(av[h].z - bf_lo(h1), av[h].w - bf_hi(h1));
            *(uint2*)(dsm + SA_HI(buf) + o * 2) = make_uint2(h0, h1);
            *(uint2*)(dsm + SA_LO(buf) + o * 2) = make_uint2(l0, l1);
        }
    };
    auto cpB = [&](int c, int buf) {
        const uint32_t dhi = smbase + SB_HI(buf) + brow * (APAD * 2) + bseg * 16;
        const uint32_t dlo = smbase + SB_LO(buf) + brow * (APAD * 2) + bseg * 16;
        const __nv_bfloat16* shi = g_w1t_hi + (size_t)brow * K_PAD + c * BK + bseg * 8;
        const __nv_bfloat16* slo = g_w1t_lo + (size_t)brow * K_PAD + c * BK + bseg * 8;
        CP_ASYNC16(dhi, shi);
        CP_ASYNC16(dhi + 32, shi + 16);
        CP_ASYNC16(dlo, slo);
        CP_ASYNC16(dlo + 32, slo + 16);
    };
    auto mmaChunk = [&](int buf) {
        #pragma unroll
        for (int s = 0; s < 2; s++) {
            const int kk = s * 16 + tid4 * 2;
            uint32_t Ah[2][4], Al[2][4];
            #pragma unroll
            for (int i = 0; i < 2; i++) {
                const int o1 = (wm * 32 + i * 16 + grp) * APAD + kk;
                const int o2 = o1 + 8 * APAD;
                Ah[i][0] = *(const uint32_t*)(dsm + SA_HI(buf) + o1 * 2);
                Ah[i][1] = *(const uint32_t*)(dsm + SA_HI(buf) + o2 * 2);
                Ah[i][2] = *(const uint32_t*)(dsm + SA_HI(buf) + (o1 + 8) * 2);
                Ah[i][3] = *(const uint32_t*)(dsm + SA_HI(buf) + (o2 + 8) * 2);
                Al[i][0] = *(const uint32_t*)(dsm + SA_LO(buf) + o1 * 2);
                Al[i][1] = *(const uint32_t*)(dsm + SA_LO(buf) + o2 * 2);
                Al[i][2] = *(const uint32_t*)(dsm + SA_LO(buf) + (o1 + 8) * 2);
                Al[i][3] = *(const uint32_t*)(dsm + SA_LO(buf) + (o2 + 8) * 2);
            }
            #pragma unroll
            for (int j = 0; j < 8; j++) {
                const int o = (wn * 64 + j * 8 + grp) * APAD + kk;
                uint32_t Bh[2], Bl[2];
                Bh[0] = *(const uint32_t*)(dsm + SB_HI(buf) + o * 2);
                Bh[1] = *(const uint32_t*)(dsm + SB_HI(buf) + (o + 8) * 2);
                Bl[0] = *(const uint32_t*)(dsm + SB_LO(buf) + o * 2);
                Bl[1] = *(const uint32_t*)(dsm + SB_LO(buf) + (o + 8) * 2);
                #pragma unroll
                for (int i = 0; i < 2; i++) {
                    mma_bf16(acc[i][j], Ah[i], Bh);
                    mma_bf16(acc[i][j], Ah[i], Bl);
                    mma_bf16(acc[i][j], Al[i], Bh);
                }
            }
        }
    };

    // ---- prologue ----
    loadA(0);
    cpB(0, 0);
    CP_COMMIT();
    stsA(0);
    CP_WAIT0();
    __syncthreads();

    // ---- GEMM1 mainloop ----
    for (int c = 0; c < NCHUNK; c++) {
        const int cur = c & 1, nxt = cur ^ 1;
        if (c + 1 < NCHUNK) {
            loadA(c + 1);
            cpB(c + 1, nxt);
            CP_COMMIT();
        }
        mmaChunk(cur);
        if (c + 1 < NCHUNK) {
            stsA(nxt);
            CP_WAIT0();
        }
        __syncthreads();
    }

    // ---- epilogue 1: ReLU + split-bf16 -> sH ----
    #pragma unroll
    for (int i = 0; i < 2; i++) {
        const int r1 = wm * 32 + i * 16 + grp;
        #pragma unroll
        for (int j = 0; j < 8; j++) {
            const int col = wn * 64 + j * 8 + tid4 * 2;
            const float f0 = fmaxf(acc[i][j][0], 0.f), f1 = fmaxf(acc[i][j][1], 0.f);
            const float f2 = fmaxf(acc[i][j][2], 0.f), f3 = fmaxf(acc[i][j][3], 0.f);
            const uint32_t h0 = pack_bf2(f0, f1);
            const uint32_t l0 = pack_bf2(f0 - bf_lo(h0), f1 - bf_hi(h0));
            const uint32_t h1w = pack_bf2(f2, f3);
            const uint32_t l1w = pack_bf2(f2 - bf_lo(h1w), f3 - bf_hi(h1w));
            const int o1 = r1 * HPAD + col;
            const int o2 = o1 + 8 * HPAD;
            *(uint32_t*)(dsm + SH_HI + o1 * 2) = h0;
            *(uint32_t*)(dsm + SH_LO + o1 * 2) = l0;
            *(uint32_t*)(dsm + SH_HI + o2 * 2) = h1w;
            *(uint32_t*)(dsm + SH_LO + o2 * 2) = l1w;
        }
    }
    // ---- W2 images -> sW (48 rows) ----
    {
        const int n  = tid >> 3;             // 0..63
        const int kq = (tid & 7) * 32;       // 0..224
        if (n < N2) {
            #pragma unroll
            for (int q = 0; q < 4; q++) {
                const uint4 vh = *(const uint4*)(g_w2t_hi + n * HID + kq + q * 8);
                const uint4 vl = *(const uint4*)(g_w2t_lo + n * HID + kq + q * 8);
                *(uint4*)(dsm + SW_HI + (n * HPAD + kq + q * 8) * 2) = vh;
                *(uint4*)(dsm + SW_LO + (n * HPAD + kq + q * 8) * 2) = vl;
            }
        }
    }
    __syncthreads();

    // ---- GEMM2: warps 0..7 compute h2[128x48] = relu(h1) @ W2t^T ----
    if (wid < 8) {
        float acc2[6][4];
        #pragma unroll
        for (int j = 0; j < 6; j++)
            #pragma unroll
            for (int q = 0; q < 4; q++)
                acc2[j][q] = 0.f;

        #pragma unroll
        for (int s = 0; s < 16; s++) {
            const int kk = s * 16 + tid4 * 2;
            const int o1 = (wid * 16 + grp) * HPAD + kk;
            const int o2 = o1 + 8 * HPAD;
            uint32_t Ah[4], Al[4];
            Ah[0] = *(const uint32_t*)(dsm + SH_HI + o1 * 2);
            Ah[1] = *(const uint32_t*)(dsm + SH_HI + o2 * 2);
            Ah[2] = *(const uint32_t*)(dsm + SH_HI + (o1 + 8) * 2);
            Ah[3] = *(const uint32_t*)(dsm + SH_HI + (o2 + 8) * 2);
            Al[0] = *(const uint32_t*)(dsm + SH_LO + o1 * 2);
            Al[1] = *(const uint32_t*)(dsm + SH_LO + o2 * 2);
            Al[2] = *(const uint32_t*)(dsm + SH_LO + (o1 + 8) * 2);
            Al[3] = *(const uint32_t*)(dsm + SH_LO + (o2 + 8) * 2);
            #pragma unroll
            for (int j = 0; j < 6; j++) {
                const int ob = (j * 8 + grp) * HPAD + kk;
                uint32_t Bh[2], Bl[2];
                Bh[0] = *(const uint32_t*)(dsm + SW_HI + ob * 2);
                Bh[1] = *(const uint32_t*)(dsm + SW_HI + (ob + 8) * 2);
                Bl[0] = *(const uint32_t*)(dsm + SW_LO + ob * 2);
                Bl[1] = *(const uint32_t*)(dsm + SW_LO + (ob + 8) * 2);
                mma_bf16(acc2[j], Ah, Bh);
                mma_bf16(acc2[j], Ah, Bl);
                mma_bf16(acc2[j], Al, Bh);
            }
        }

        // ---- epilogue 2: h2 = D2 + b2 ; g_h2 = h2 ; out = alpha*h2 ----
        const int r1 = blockRow + wid * 16 + grp;
        const int r2 = r1 + 8;
        #pragma unroll
        for (int j = 0; j < 5; j++) {          // cols 0..39 only
            const int col = j * 8 + tid4 * 2;
            const float b0 = s_b2[col], b1v = s_b2[col + 1];
            if (r1 < N_NODES) {
                const float v0 = acc2[j][0] + b0, v1 = acc2[j][1] + b1v;
                *(float2*)(g_h2 + (size_t)r1 * C_OUT + col) = make_float2(v0, v1);
                *(float2*)(out  + (size_t)r1 * C_OUT + col) = make_float2(ALPHA0 * v0, ALPHA0 * v1);
            }
            if (r2 < N_NODES) {
                const float v2 = acc2[j][2] + b0, v3 = acc2[j][3] + b1v;
                *(float2*)(g_h2 + (size_t)r2 * C_OUT + col) = make_float2(v2, v3);
                *(float2*)(out  + (size_t)r2 * C_OUT + col) = make_float2(ALPHA0 * v2, ALPHA0 * v3);
            }
        }
    }
}

// ---------------------------------------------------------------------------
// Edge scatter-add: out[row] += val * h2[col]  (10 threads/edge, red.v4)
// ---------------------------------------------------------------------------
__global__ void __launch_bounds__(256) edge_kernel(
    const int* __restrict__ erow,
    const int* __restrict__ ecol,
    const float* __restrict__ eval,
    float* __restrict__ out,
    long long num_edges)
{
    const long long gid = (long long)blockIdx.x * blockDim.x + threadIdx.x;
    const long long e = gid / 10;
    if (e >= num_edges) return;
    const int sub = (int)(gid % 10);

    const int r = erow[e];
    const int c = ecol[e];
    const float v = eval[e];

    const float4 h = reinterpret_cast<const float4*>(g_h2 + (size_t)c * C_OUT)[sub];
    float* o = out + (size_t)r * C_OUT + sub * 4;
    asm volatile("red.global.add.v4.f32 [%0], {%1, %2, %3, %4};"
                 :: "l"(o), "f"(v * h.x), "f"(v * h.y), "f"(v * h.z), "f"(v * h.w)
                 : "memory");
}

// ---------------------------------------------------------------------------
// log_softmax over C=40, one warp per row, in place.
// ---------------------------------------------------------------------------
__global__ void __launch_bounds__(256) logsoftmax_kernel(float* __restrict__ out)
{
    const int warp = (blockIdx.x * blockDim.x + threadIdx.x) >> 5;
    const int lane = threadIdx.x & 31;
    if (warp >= N_NODES) return;

    float* row = out + (size_t)warp * C_OUT;
    const float v0 = (lane < C_OUT) ? row[lane] : -__int_as_float(0x7f800000);
    const float v1 = (lane + 32 < C_OUT) ? row[lane + 32] : -__int_as_float(0x7f800000);

    float m = fmaxf(v0, v1);
    #pragma unroll
    for (int o = 16; o > 0; o >>= 1)
        m = fmaxf(m, __shfl_xor_sync(0xffffffffu, m, o));

    float s = ((lane < C_OUT) ? expf(v0 - m) : 0.f)
            + ((lane + 32 < C_OUT) ? expf(v1 - m) : 0.f);
    #pragma unroll
    for (int o = 16; o > 0; o >>= 1)
        s += __shfl_xor_sync(0xffffffffu, s, o);

    const float lse = m + logf(s);
    if (lane < C_OUT) row[lane] = v0 - lse;
    if (lane + 32 < C_OUT) row[lane + 32] = v1 - lse;
}

// ---------------------------------------------------------------------------
// Inputs: x, W1, b1, W2, b2, edge_row, edge_col, edge_val
// ---------------------------------------------------------------------------
extern "C" void kernel_launch(void* const* d_in, const int* in_sizes, int n_in,
                              void* d_out, int out_size)
{
    const float* x    = (const float*)d_in[0];
    const float* W1   = (const float*)d_in[1];
    const float* b1   = (const float*)d_in[2];
    const float* W2   = (const float*)d_in[3];
    const float* b2   = (const float*)d_in[4];
    const int*   erow = (const int*)d_in[5];
    const int*   ecol = (const int*)d_in[6];
    const float* eval = (const float*)d_in[7];
    float* out = (float*)d_out;

    const long long E = in_sizes[5];

    cudaFuncSetAttribute(fused_kernel,
                         cudaFuncAttributeMaxDynamicSharedMemorySize, DSMEM_BYTES);

    // prep weight images
    {
        const int total = HID * K_PAD + N2 * HID;
        prep_kernel<<<(total + 255) / 256, 256>>>(W1, b1, W2);
    }
    // fused GEMM1+GEMM2 -> g_h2, out = alpha*h2
    {
        const int blocks = (N_NODES + BM - 1) / BM;
        fused_kernel<<<blocks, 512, DSMEM_BYTES>>>(x, b2, out);
    }
    // edge scatter-add (vector red)
    {
        const long long total = E * 10;
        edge_kernel<<<(int)((total + 255) / 256), 256>>>(erow, ecol, eval, out, E);
    }
    // log_softmax
    {
        const long long threads = (long long)N_NODES * 32;
        logsoftmax_kernel<<<(int)((threads + 255) / 256), 256>>>(out);
    }
}